// round 3
// baseline (speedup 1.0000x reference)
#include <cuda_runtime.h>
#include <cstddef>

#define NN 100000
#define NE 1600000
#define DIM 64
#define N_LAYERS 6

// ---------------- scratch (no allocations allowed) ----------------
__device__ float g_h1[NN * DIM];
__device__ float g_h2[NN * DIM];
__device__ int   g_deg[NN];
__device__ int   g_off[NN + 1];
__device__ int   g_cur[NN];
__device__ int   g_csrc[NE];

// ---------------- CSR build ----------------
__global__ void k_init_deg() {
    int i = blockIdx.x * blockDim.x + threadIdx.x;
    if (i < NN) g_deg[i] = 0;
}

// edge_index delivered as int32, layout [2, NE]: row 0 = src, row 1 = dst
__global__ void k_count(const int* __restrict__ ei) {
    int e = blockIdx.x * blockDim.x + threadIdx.x;
    if (e < NE) {
        int dst = ei[NE + e];
        if ((unsigned)dst < (unsigned)NN) atomicAdd(&g_deg[dst], 1);
    }
}

// single-block exclusive scan of g_deg -> g_off, copy to g_cur
__global__ void k_scan() {
    __shared__ int sums[1024];
    int t = threadIdx.x;
    const int C = (NN + 1023) / 1024;  // 98
    int start = t * C;
    int end = start + C; if (end > NN) end = NN;
    if (start > NN) start = NN;
    int s = 0;
    for (int i = start; i < end; i++) s += g_deg[i];
    sums[t] = s;
    __syncthreads();
    // Hillis-Steele inclusive scan
    for (int off = 1; off < 1024; off <<= 1) {
        int v = (t >= off) ? sums[t - off] : 0;
        __syncthreads();
        sums[t] += v;
        __syncthreads();
    }
    int base = (t == 0) ? 0 : sums[t - 1];
    for (int i = start; i < end; i++) {
        int d = g_deg[i];
        g_off[i] = base;
        g_cur[i] = base;
        base += d;
    }
    if (t == 1023) g_off[NN] = base;  // == NE
}

__global__ void k_fill(const int* __restrict__ ei) {
    int e = blockIdx.x * blockDim.x + threadIdx.x;
    if (e < NE) {
        int src = ei[e];
        int dst = ei[NE + e];
        if ((unsigned)dst < (unsigned)NN && (unsigned)src < (unsigned)NN) {
            int p = atomicAdd(&g_cur[dst], 1);
            g_csrc[p] = src;
        }
    }
}

// ---------------- fused SAGE layer ----------------
// warp-per-node: gather-max neighbors (float2 per lane), stage z=[agg,h] in smem,
// then out[j] = bias[j] + sum_k z[k]*wt[k][j], wt = [Wl;Wr] transposed in smem.
// buffer select codes: 0 = external pointer, 1 = g_h1, 2 = g_h2
__global__ __launch_bounds__(512) void k_sage(
    const float* __restrict__ hin_ext, float* __restrict__ hout_ext,
    int sel_in, int sel_out,
    const float* __restrict__ Wl, const float* __restrict__ bl,
    const float* __restrict__ Wr, int do_relu)
{
    __shared__ float wt[128 * 64];   // wt[k*64+j] : k<64 -> Wl[j][k], k>=64 -> Wr[j][k-64]
    __shared__ float zbuf[16][128];
    __shared__ float bias[64];

    const float* hin  = (sel_in  == 0) ? hin_ext  : (sel_in  == 1 ? g_h1 : g_h2);
    float*       hout = (sel_out == 0) ? hout_ext : (sel_out == 1 ? g_h1 : g_h2);

    int tid = threadIdx.x;
    for (int i = tid; i < 64 * 64; i += 512) {
        int j = i >> 6, k = i & 63;          // i = j*64 + k
        wt[k * 64 + j]        = Wl[i];
        wt[(64 + k) * 64 + j] = Wr[i];
    }
    if (tid < 64) bias[tid] = bl[tid];
    __syncthreads();

    int w = tid >> 5, lane = tid & 31;
    int j0 = lane * 2;
    const int ntiles = (NN + 15) / 16;

    for (int tile = blockIdx.x; tile < ntiles; tile += gridDim.x) {
        int node = tile * 16 + w;
        if (node < NN) {
            int beg = g_off[node];
            int end = g_off[node + 1];
            float ax = -3.4e38f, ay = -3.4e38f;
            for (int i = beg; i < end; i++) {
                int s = g_csrc[i];
                float2 v = *(const float2*)(hin + (size_t)s * DIM + j0);
                ax = fmaxf(ax, v.x);
                ay = fmaxf(ay, v.y);
            }
            if (beg == end) { ax = 0.f; ay = 0.f; }   // no in-edges -> 0
            float2 hv = *(const float2*)(hin + (size_t)node * DIM + j0);
            zbuf[w][j0]          = ax;
            zbuf[w][j0 + 1]      = ay;
            zbuf[w][64 + j0]     = hv.x;
            zbuf[w][64 + j0 + 1] = hv.y;
        }
        __syncwarp();
        if (node < NN) {
            float ox = bias[j0], oy = bias[j0 + 1];
            #pragma unroll 8
            for (int k = 0; k < 128; k++) {
                float a = zbuf[w][k];
                float2 ww = *(const float2*)&wt[k * 64 + j0];
                ox = fmaf(a, ww.x, ox);
                oy = fmaf(a, ww.y, oy);
            }
            if (do_relu) { ox = fmaxf(ox, 0.f); oy = fmaxf(oy, 0.f); }
            float2 o; o.x = ox; o.y = oy;
            *(float2*)(hout + (size_t)node * DIM + j0) = o;
        }
        __syncwarp();
    }
}

// ---------------- launch ----------------
extern "C" void kernel_launch(void* const* d_in, const int* in_sizes, int n_in,
                              void* d_out, int out_size)
{
    const float* x  = (const float*)d_in[0];
    const int*   ei = (const int*)d_in[1];
    const float* Wl = (const float*)d_in[2];
    const float* bl = (const float*)d_in[3];
    const float* Wr = (const float*)d_in[4];
    float*       out = (float*)d_out;

    k_init_deg<<<(NN + 255) / 256, 256>>>();
    k_count<<<(NE + 255) / 256, 256>>>(ei);
    k_scan<<<1, 1024>>>();
    k_fill<<<(NE + 255) / 256, 256>>>(ei);

    const int GRID = 592;  // 148 SMs * 4 persistent blocks
    // ping-pong: ext(x) -> g_h1 -> g_h2 -> g_h1 -> g_h2 -> g_h1 -> ext(out)
    int sel_in = 0, sel_out = 1;
    for (int l = 0; l < N_LAYERS; l++) {
        int so = (l == N_LAYERS - 1) ? 0 : sel_out;
        k_sage<<<GRID, 512>>>(x, out, sel_in, so,
                              Wl + (size_t)l * DIM * DIM,
                              bl + (size_t)l * DIM,
                              Wr + (size_t)l * DIM * DIM,
                              (l < N_LAYERS - 1) ? 1 : 0);
        if (l < N_LAYERS - 1) {
            sel_in = sel_out;
            sel_out = (sel_out == 1) ? 2 : 1;
        }
    }
}